// round 1
// baseline (speedup 1.0000x reference)
#include <cuda_runtime.h>

// CTC loss forward, shapes fixed by the problem:
//   log_probs [T=256, B=64, C=8000] f32, targets [B, L=32] i32,
//   input_lengths [B] i32, target_lengths [B] i32  ->  scalar f32 (mean loss/len)
//
// One warp per batch element. Lane l owns lattice states 2l (blank) and 2l+1
// (label l); lane 31 additionally owns state 64 (final blank). Even states
// never take the skip transition (ext==BLANK), so per step each lane needs:
//   - one uniform load  lp[t,b,0]          (blank emission, warp-broadcast)
//   - one scattered load lp[t,b,tgt[l]]    (label emission)
// Emissions are software-pipelined D steps ahead in registers to hide DRAM
// latency; the per-step critical path is shfl_up + one fused 3-way logaddexp.

#define NEGV (-1e9f)

constexpr int T_MAX = 256;
constexpr int B_SZ  = 64;
constexpr int C_SZ  = 8000;
constexpr int L_MAX = 32;
constexpr int PF_D  = 8;   // emission prefetch depth (register ring)

__device__ float g_loss[B_SZ];

__device__ __forceinline__ float lae2(float x, float y) {
    float m = fmaxf(x, y);
    float d = fabsf(x - y);
    return m + __logf(1.0f + __expf(-d));
}
__device__ __forceinline__ float lae3(float x, float y, float z) {
    float m = fmaxf(fmaxf(x, y), z);
    return m + __logf(__expf(x - m) + __expf(y - m) + __expf(z - m));
}

__global__ void __launch_bounds__(32, 1)
ctc_alpha_kernel(const float* __restrict__ lp,
                 const int*   __restrict__ targets,
                 const int*   __restrict__ in_len,
                 const int*   __restrict__ tgt_len) {
    const int b = blockIdx.x;
    const int l = threadIdx.x;          // lane 0..31
    const size_t BC = (size_t)B_SZ * C_SZ;
    const float* lpb = lp + (size_t)b * C_SZ;   // index as lpb[t*BC + c]

    const int tl   = tgt_len[b];
    const int last = in_len[b] - 1;     // alpha needed at t = input_len-1 (>=128)

    // ext for odd state 2l+1: label l if l < tl else blank
    const int c1  = (l < tl) ? targets[b * L_MAX + l] : 0;
    const int c1m = __shfl_up_sync(0xffffffffu, c1, 1);
    const bool skip1 = (c1 != 0) && ((l == 0) || (c1 != c1m));

    // t = 0 init: a0[0] = lp0[blank]; a0[1] = lp0[tgt0] (tl>0); rest NEG
    float a0 = NEGV, a1 = NEGV, a2 = NEGV;
    if (l == 0) {
        a0 = lpb[0];
        a1 = (tl > 0) ? lpb[c1] : NEGV;
    }

    // prefetch emissions for t = 1..PF_D (last >= 128 >> PF_D, no clamp needed)
    float eb[PF_D], e1[PF_D];
#pragma unroll
    for (int k = 0; k < PF_D; k++) {
        size_t off = (size_t)(1 + k) * BC;
        eb[k] = __ldg(lpb + off);        // blank emission
        e1[k] = __ldg(lpb + off + c1);   // label emission
    }

    for (int t = 1; t <= last; ++t) {
        const float emb = eb[0];
        const float em1 = e1[0];
#pragma unroll
        for (int k = 0; k < PF_D - 1; k++) { eb[k] = eb[k + 1]; e1[k] = e1[k + 1]; }
        int tn = t + PF_D; if (tn > last) tn = last;   // clamped dummy addr, value unused
        const size_t off = (size_t)tn * BC;
        eb[PF_D - 1] = __ldg(lpb + off);
        e1[PF_D - 1] = __ldg(lpb + off + c1);

        // previous-step alpha of state 2l-1 lives in lane l-1's a1
        float pa1 = __shfl_up_sync(0xffffffffu, a1, 1);
        if (l == 0) pa1 = NEGV;          // also covers s=1's alpha[-1] term

        const float n0 = lae2(a0, pa1) + emb;                       // even state 2l
        const float n1 = (skip1 ? lae3(a1, a0, pa1)
                                : lae2(a1, a0)) + em1;              // odd state 2l+1
        const float n2 = lae2(a2, a1) + emb;                        // state 64 (lane 31)
        a0 = n0; a1 = n1; a2 = n2;
    }

    // final: i_blank = 2*tl -> even state (lane tl, or a2@lane31 if tl==32)
    //        i_char  = 2*tl-1 -> odd state (lane tl-1)
    const float vb_lo = __shfl_sync(0xffffffffu, a0, tl & 31);
    const float vb_hi = __shfl_sync(0xffffffffu, a2, 31);
    const float vb = (tl >= 32) ? vb_hi : vb_lo;
    const int icl = (tl > 0) ? (tl - 1) : 0;
    const float vc = __shfl_sync(0xffffffffu, a1, icl);
    const float total = (tl > 0) ? lae2(vb, vc) : vb;

    if (l == 0) {
        const float denom = (float)((tl > 0) ? tl : 1);
        g_loss[b] = -total / denom;
    }
}

__global__ void ctc_reduce_kernel(float* __restrict__ out) {
    // fixed-order sum: deterministic
    float s = 0.0f;
    for (int i = 0; i < B_SZ; i++) s += g_loss[i];
    out[0] = s / (float)B_SZ;
}

extern "C" void kernel_launch(void* const* d_in, const int* in_sizes, int n_in,
                              void* d_out, int out_size) {
    const float* log_probs   = (const float*)d_in[0];
    const int*   targets     = (const int*)d_in[1];
    const int*   input_len   = (const int*)d_in[2];
    const int*   target_len  = (const int*)d_in[3];
    float* out = (float*)d_out;
    (void)in_sizes; (void)n_in; (void)out_size;

    ctc_alpha_kernel<<<B_SZ, 32>>>(log_probs, targets, input_len, target_len);
    ctc_reduce_kernel<<<1, 1>>>(out);
}

// round 3
// speedup vs baseline: 3.2149x; 3.2149x over previous
#include <cuda_runtime.h>

// CTC loss forward in the LINEAR (probability) domain with exact pow2 rescaling.
//   log_probs [T=256, B=64, C=8000] f32 -> scalar mean(loss/target_len)
//
// One warp per batch. Lane l owns states 2l (blank) and 2l+1 (label l);
// lane 31 also owns state 64. Per-step recursion is adds+muls:
//   n0 = (a0 + pa1) * pb
//   n1 = (a1 + a0 (+ pa1 if skip)) * p1
//   n2 = (a2 + a1) * pb            (lane 31 only, harmless elsewhere)
// pa1 = shfl_up(a1). Emissions (log space) are prefetched 16 steps ahead in a
// register ring; exp() happens at consumption, off the dependent chain.
// Every 4 steps: warp max via redux.sync.max.s32 on the float bits (alphas are
// >= 0, so int ordering == float ordering), renormalize max to ~2^32 by an
// exact power of two, accumulate integer exponent. Loop runs a fixed 256
// iterations; alpha at t=input_len-1 is captured by predicated snapshot.

constexpr int B_SZ  = 64;
constexpr int C_SZ  = 8000;
constexpr int L_MAX = 32;
constexpr int PF    = 16;   // emission prefetch depth

__device__ float g_loss[B_SZ];
__device__ int   g_count;

__device__ __forceinline__ int warp_max_s32(int v) {
    int r;
    asm volatile("redux.sync.max.s32 %0, %1, 0xffffffff;" : "=r"(r) : "r"(v));
    return r;
}

__global__ void __launch_bounds__(32, 1)
ctc_fused_kernel(const float* __restrict__ lp,
                 const int*   __restrict__ targets,
                 const int*   __restrict__ in_len,
                 const int*   __restrict__ tgt_len,
                 float*       __restrict__ out) {
    const int b = blockIdx.x;
    const int l = threadIdx.x;
    const size_t BC = (size_t)B_SZ * C_SZ;
    const float* lpb = lp + (size_t)b * C_SZ;   // lpb[t*BC + c]

    const int tl   = tgt_len[b];
    const int last = in_len[b] - 1;             // in [128, 255]

    // label class for odd state 2l+1 (blank past target_len), skip flag
    const int  c1   = (l < tl) ? targets[b * L_MAX + l] : 0;
    const int  c1m  = __shfl_up_sync(0xffffffffu, c1, 1);
    const bool skip1 = (c1 != 0) && ((l == 0) || (c1 != c1m));

    // t = 0 init (prob domain)
    float a0 = 0.f, a1 = 0.f, a2 = 0.f;
    if (l == 0) {
        a0 = __expf(lpb[0]);
        a1 = (tl > 0) ? __expf(lpb[c1]) : 0.f;
    }

    // prefetch emissions (log space) for t = 1..PF
    float eb[PF], e1[PF];
#pragma unroll
    for (int k = 0; k < PF; k++) {
        size_t off = (size_t)(1 + k) * BC;
        eb[k] = __ldg(lpb + off);
        e1[k] = __ldg(lpb + off + c1);
    }

    int   se  = 0;                    // accumulated scale exponent (base 2)
    float fa0 = 0.f, fa1 = 0.f, fa2 = 0.f;
    int   fe  = 0;                    // snapshot of se at t == last

    #pragma unroll 16
    for (int t = 1; t <= 256; ++t) {
        const float pb = __expf(eb[0]);     // off critical chain (value 16 iters old)
        const float p1 = __expf(e1[0]);
#pragma unroll
        for (int k = 0; k < PF - 1; k++) { eb[k] = eb[k + 1]; e1[k] = e1[k + 1]; }
        {
            int tn = t + PF; tn = (tn > 255) ? 255 : tn;   // clamped dup loads, values unused
            const size_t off = (size_t)tn * BC;
            eb[PF - 1] = __ldg(lpb + off);
            e1[PF - 1] = __ldg(lpb + off + c1);
        }

        float pa1 = __shfl_up_sync(0xffffffffu, a1, 1);
        if (l == 0) pa1 = 0.f;

        const float s01 = a0 + pa1;
        const float n0  = s01 * pb;
        const float n1  = (skip1 ? (a1 + s01) : (a1 + a0)) * p1;
        const float n2  = (a2 + a1) * pb;
        a0 = n0; a1 = n1; a2 = n2;

        if ((t & 3) == 0) {
            // warp-wide max alpha (nonnegative floats: int bit order == value order)
            const int mi  = warp_max_s32(__float_as_int(fmaxf(a0, fmaxf(a1, a2))));
            const int ebi = (mi >> 23) & 0xff;                      // biased exponent
            const float f = __int_as_float((286 - ebi) << 23);      // 2^(32 - E), exact
            a0 *= f; a1 *= f; a2 *= f;
            se += ebi - 159;                                        // E - 32
        }
        if (t == last) { fa0 = a0; fa1 = a1; fa2 = a2; fe = se; }
    }

    // final states: i_blank = 2*tl (even; state 64 lives in a2@lane31),
    //               i_char  = 2*tl - 1 (odd; a1 @ lane tl-1)
    const float vbl = __shfl_sync(0xffffffffu, fa0, tl & 31);
    const float vbh = __shfl_sync(0xffffffffu, fa2, 31);
    const float vb  = (tl >= 32) ? vbh : vbl;
    const int   icl = (tl > 0) ? (tl - 1) : 0;
    const float vc  = __shfl_sync(0xffffffffu, fa1, icl);
    const float tot = (tl > 0) ? (vb + vc) : vb;

    if (l == 0) {
        const float total_log = logf(tot) + (float)fe * 0.69314718055994531f;
        const int   denom     = (tl > 0) ? tl : 1;
        g_loss[b] = -total_log / (float)denom;
        __threadfence();
        const int old = atomicAdd(&g_count, 1);
        if (old == B_SZ - 1) {
            g_count = 0;            // reset for next graph replay
            __threadfence();
            float s = 0.f;
            for (int i = 0; i < B_SZ; i++) s += __ldcg((const float*)&g_loss[i]);
            out[0] = s / (float)B_SZ;
        }
    }
}

extern "C" void kernel_launch(void* const* d_in, const int* in_sizes, int n_in,
                              void* d_out, int out_size) {
    const float* log_probs  = (const float*)d_in[0];
    const int*   targets    = (const int*)d_in[1];
    const int*   input_len  = (const int*)d_in[2];
    const int*   target_len = (const int*)d_in[3];
    float* out = (float*)d_out;
    (void)in_sizes; (void)n_in; (void)out_size;

    ctc_fused_kernel<<<B_SZ, 32>>>(log_probs, targets, input_len, target_len, out);
}